// round 10
// baseline (speedup 1.0000x reference)
#include <cuda_runtime.h>
#include <cuda_fp16.h>
#include <math.h>
#include <stdint.h>

#define NN 50000
#define EE 500000
#define ET (EE + NN)
#define GG 64
#define SCAL 96
#define DD 32
#define INDIM 256
#define CC 128
#define H1N 4
#define NCLS 5

// ---------------- scratch (device globals; no allocation allowed) ----------
__device__ __half g_featsh[NN * INDIM];      // [N,256] fp16
__device__ __half g_h1h[NN * H1N * CC];      // [N,512] fp16
__device__ __half g_out1h[NN * H1N * CC];    // [N,512] fp16
__device__ __half g_h2h[NN * CC];            // [N,128] fp16
__device__ float  g_asrc1[NN * H1N];
__device__ float  g_adst1[NN * H1N];
__device__ float  g_asrc2[NN];
__device__ float  g_adst2[NN];
__device__ unsigned int g_pooledu[GG * CC];  // order-preserving uint max
__device__ float  g_P1[INDIM * 8];           // [k][j]  j = h*2 + (0:src,1:dst)
// CSR scratch
__device__ int g_deg[NN];
__device__ int g_rowptr[NN + 1];
__device__ int g_cursor[NN];
__device__ int g_csrc[ET];

// order-preserving float<->uint for atomicMax
__device__ __forceinline__ unsigned int fkey(float v) {
    unsigned int u = __float_as_uint(v);
    return u ^ ((u & 0x80000000u) ? 0xFFFFFFFFu : 0x80000000u);
}
__device__ __forceinline__ float finv(unsigned int k) {
    unsigned int u = (k & 0x80000000u) ? (k ^ 0x80000000u) : ~k;
    return __uint_as_float(u);
}

// ---------------- fused init: zero deg/asrc2/adst2, init pooled, prep1 ------
__global__ void k_init(const float* __restrict__ W1, const float* __restrict__ as1,
                       const float* __restrict__ ad1) {
    int idx = blockIdx.x * 256 + threadIdx.x;
    if (idx < NN) { g_deg[idx] = 0; g_asrc2[idx] = 0.f; g_adst2[idx] = 0.f; }
    if (idx < GG * CC) g_pooledu[idx] = 0u;
    if (idx < 2048) {
        int kk = idx >> 3, j = idx & 7, h = j >> 1;
        const float* av = (j & 1) ? ad1 : as1;
        float s = 0.f;
        for (int c = 0; c < 128; c++) s += W1[kk * 512 + h * 128 + c] * av[h * 128 + c];
        g_P1[kk * 8 + j] = s;
    }
}

// ---------------- CSR build -------------------------------------------------
__global__ void k_deg(const int* __restrict__ ei) {
    int e = blockIdx.x * blockDim.x + threadIdx.x;
    if (e >= ET) return;
    int d = (e < EE) ? ei[EE + e] : (e - EE);
    atomicAdd(&g_deg[d], 1);
}

// single block, 1024 threads = 32 warps, coalesced two-phase scan
__global__ void k_scan() {
    __shared__ int wsum[32], wbase[32];
    int t = threadIdx.x, w = t >> 5, lane = t & 31;
    const int CHUNK = 1568;
    int start = w * CHUNK;
    int lim = start + CHUNK; if (lim > NN) lim = NN;
    int s = 0;
    for (int i = start + lane; i < lim; i += 32) s += g_deg[i];
#pragma unroll
    for (int o = 16; o; o >>= 1) s += __shfl_xor_sync(0xffffffffu, s, o);
    if (lane == 0) wsum[w] = s;
    __syncthreads();
    if (w == 0) {
        int v = wsum[lane];
        int incl = v;
#pragma unroll
        for (int o = 1; o < 32; o <<= 1) {
            int u = __shfl_up_sync(0xffffffffu, incl, o);
            if (lane >= o) incl += u;
        }
        wbase[lane] = incl - v;
        if (lane == 31) g_rowptr[NN] = incl;
    }
    __syncthreads();
    int running = wbase[w];
    for (int i0 = start; i0 < lim; i0 += 32) {
        int idx = i0 + lane;
        int v = (idx < lim) ? g_deg[idx] : 0;
        int incl = v;
#pragma unroll
        for (int o = 1; o < 32; o <<= 1) {
            int u = __shfl_up_sync(0xffffffffu, incl, o);
            if (lane >= o) incl += u;
        }
        int excl = incl - v;
        if (idx < lim) { g_rowptr[idx] = running + excl; g_cursor[idx] = running + excl; }
        running += __shfl_sync(0xffffffffu, incl, 31);
    }
}

__global__ void k_fill(const int* __restrict__ ei) {
    int e = blockIdx.x * blockDim.x + threadIdx.x;
    if (e >= ET) return;
    int s, d;
    if (e < EE) { s = ei[e]; d = ei[EE + e]; } else { s = d = e - EE; }
    int pos = atomicAdd(&g_cursor[d], 1);
    g_csrc[pos] = s;
}

// ---------------- feature build + LN + fused conv1 attention logits ---------
__global__ void k_feats(const float* __restrict__ xs,
                        const int* __restrict__ xop, const int* __restrict__ xsrc,
                        const int* __restrict__ xsink, const int* __restrict__ xstr,
                        const int* __restrict__ xpay,
                        const float* __restrict__ eop, const float* __restrict__ esrc,
                        const float* __restrict__ esink, const float* __restrict__ estr,
                        const float* __restrict__ epay,
                        const float* __restrict__ ln_g, const float* __restrict__ ln_b) {
    int n = blockIdx.x;
    int t = threadIdx.x;  // 256 threads
    int w = t >> 5, lane = t & 31;
    float v;
    if (t < SCAL) {
        v = xs[n * SCAL + t];
    } else {
        int grp = (t - SCAL) / DD;
        int d = (t - SCAL) % DD;
        const int* idxp; const float* tab; int L;
        switch (grp) {
            case 0: idxp = xop + n * 16; tab = eop; L = 16; break;
            case 1: idxp = xsrc + n * 8; tab = esrc; L = 8; break;
            case 2: idxp = xsink + n * 8; tab = esink; L = 8; break;
            case 3: idxp = xstr + n * 8; tab = estr; L = 8; break;
            default: idxp = xpay + n * 8; tab = epay; L = 8; break;
        }
        float s = 0.f, cnt = 0.f;
        for (int l = 0; l < L; l++) {
            int id = idxp[l];
            if (id != 0) { s += tab[id * DD + d]; cnt += 1.f; }
        }
        v = s / (cnt + 1e-9f);
    }
    __shared__ float smA[8], smB[8];
    __shared__ float sm8[8][8];
    float s1 = v, s2 = v * v;
#pragma unroll
    for (int o = 16; o; o >>= 1) {
        s1 += __shfl_xor_sync(0xffffffffu, s1, o);
        s2 += __shfl_xor_sync(0xffffffffu, s2, o);
    }
    if (lane == 0) { smA[w] = s1; smB[w] = s2; }
    __syncthreads();
    float S = 0.f, S2 = 0.f;
#pragma unroll
    for (int i = 0; i < 8; i++) { S += smA[i]; S2 += smB[i]; }
    float mu = S * (1.f / 256.f);
    float var = S2 * (1.f / 256.f) - mu * mu;
    float o = (v - mu) * rsqrtf(var + 1e-5f) * ln_g[t] + ln_b[t];
    g_featsh[n * INDIM + t] = __float2half_rn(o);
    float pj[8];
#pragma unroll
    for (int j = 0; j < 8; j++) pj[j] = o * g_P1[t * 8 + j];
#pragma unroll
    for (int j = 0; j < 8; j++)
#pragma unroll
        for (int off = 16; off; off >>= 1) pj[j] += __shfl_xor_sync(0xffffffffu, pj[j], off);
    if (lane == 0) {
#pragma unroll
        for (int j = 0; j < 8; j++) sm8[w][j] = pj[j];
    }
    __syncthreads();
    if (t < 8) {
        float s = 0.f;
#pragma unroll
        for (int i = 0; i < 8; i++) s += sm8[i][t];
        int h = t >> 1;
        if (t & 1) g_adst1[n * 4 + h] = s;
        else       g_asrc1[n * 4 + h] = s;
    }
}

// ---------------- fp16 tensor-core GEMM + optional att-logit epilogue -------
#define MMA_F16(d0,d1,d2,d3,a0,a1,a2,a3,b0,b1) \
    asm volatile("mma.sync.aligned.m16n8k16.row.col.f32.f16.f16.f32 " \
                 "{%0,%1,%2,%3},{%4,%5,%6,%7},{%8,%9},{%0,%1,%2,%3};" \
                 : "+f"(d0), "+f"(d1), "+f"(d2), "+f"(d3) \
                 : "r"(a0), "r"(a1), "r"(a2), "r"(a3), "r"(b0), "r"(b1))

__device__ __forceinline__ uint32_t pack_h2(float x, float y) {
    __half2 h = __floats2half2_rn(x, y);
    return *(uint32_t*)&h;
}

__global__ void __launch_bounds__(256) k_hgemm(const __half* __restrict__ A,
                                               const float* __restrict__ B,
                                               __half* __restrict__ C, int M, int N, int K,
                                               const float* __restrict__ attS,
                                               const float* __restrict__ attD) {
    __shared__ uint32_t As2[2][128][20];
    __shared__ uint32_t Bs2[2][128][20];
    int tid = threadIdx.x;
    int wid = tid >> 5, lane = tid & 31;
    int wm = (wid & 3) * 32;
    int wn = (wid >> 2) * 64;
    int gid = lane >> 2, tig = lane & 3;
    int row0 = blockIdx.y * 128, col0 = blockIdx.x * 128;
    float acc[2][8][4];
#pragma unroll
    for (int i = 0; i < 2; i++)
#pragma unroll
        for (int j = 0; j < 8; j++)
#pragma unroll
            for (int q = 0; q < 4; q++) acc[i][j][q] = 0.f;

    int T = K >> 5;
    {
#pragma unroll
        for (int r = 0; r < 8; r++) {
            int u = tid + 256 * r;
            int m = u >> 4, q = u & 15;
            int gm = row0 + m;
            As2[0][m][q] = (gm < M) ? ((const uint32_t*)(A + (size_t)gm * K))[q] : 0u;
        }
#pragma unroll
        for (int r = 0; r < 8; r++) {
            int u = tid + 256 * r;
            int n = u & 127, q = u >> 7;
            float b0v = B[(size_t)(2 * q) * N + col0 + n];
            float b1v = B[(size_t)(2 * q + 1) * N + col0 + n];
            Bs2[0][n][q] = pack_h2(b0v, b1v);
        }
    }
    __syncthreads();

    for (int t = 0; t < T; t++) {
        int cur = t & 1;
        uint32_t ra[8], rb[8];
        if (t + 1 < T) {
            int k0 = (t + 1) << 5;
#pragma unroll
            for (int r = 0; r < 8; r++) {
                int u = tid + 256 * r;
                int m = u >> 4, q = u & 15;
                int gm = row0 + m;
                ra[r] = (gm < M) ? ((const uint32_t*)(A + (size_t)gm * K + k0))[q] : 0u;
            }
#pragma unroll
            for (int r = 0; r < 8; r++) {
                int u = tid + 256 * r;
                int n = u & 127, q = u >> 7;
                float b0v = B[(size_t)(k0 + 2 * q) * N + col0 + n];
                float b1v = B[(size_t)(k0 + 2 * q + 1) * N + col0 + n];
                rb[r] = pack_h2(b0v, b1v);
            }
        }
#pragma unroll
        for (int ks = 0; ks < 2; ks++) {
            int kb = ks * 8;
            uint32_t a[2][4];
#pragma unroll
            for (int mi = 0; mi < 2; mi++) {
                int r = wm + mi * 16 + gid;
                a[mi][0] = As2[cur][r][kb + tig];
                a[mi][1] = As2[cur][r + 8][kb + tig];
                a[mi][2] = As2[cur][r][kb + tig + 4];
                a[mi][3] = As2[cur][r + 8][kb + tig + 4];
            }
#pragma unroll
            for (int ni = 0; ni < 8; ni++) {
                uint32_t b0 = Bs2[cur][wn + ni * 8 + gid][kb + tig];
                uint32_t b1 = Bs2[cur][wn + ni * 8 + gid][kb + tig + 4];
#pragma unroll
                for (int mi = 0; mi < 2; mi++) {
                    MMA_F16(acc[mi][ni][0], acc[mi][ni][1], acc[mi][ni][2], acc[mi][ni][3],
                            a[mi][0], a[mi][1], a[mi][2], a[mi][3], b0, b1);
                }
            }
        }
        if (t + 1 < T) {
            int nxt = 1 - cur;
#pragma unroll
            for (int r = 0; r < 8; r++) {
                int u = tid + 256 * r;
                int m = u >> 4, q = u & 15;
                As2[nxt][m][q] = ra[r];
            }
#pragma unroll
            for (int r = 0; r < 8; r++) {
                int u = tid + 256 * r;
                int n = u & 127, q = u >> 7;
                Bs2[nxt][n][q] = rb[r];
            }
        }
        __syncthreads();
    }
#pragma unroll
    for (int mi = 0; mi < 2; mi++) {
#pragma unroll
        for (int ni = 0; ni < 8; ni++) {
            int r = row0 + wm + mi * 16 + gid;
            int c = col0 + wn + ni * 8 + tig * 2;
            if (r < M)
                *(__half2*)(C + (size_t)r * N + c) = __floats2half2_rn(acc[mi][ni][0], acc[mi][ni][1]);
            if (r + 8 < M)
                *(__half2*)(C + (size_t)(r + 8) * N + c) = __floats2half2_rn(acc[mi][ni][2], acc[mi][ni][3]);
        }
    }
    // optional fused attention-logit epilogue (conv2: per-row dot with att vecs)
    if (attS) {
#pragma unroll
        for (int mi = 0; mi < 2; mi++) {
#pragma unroll
            for (int hf = 0; hf < 2; hf++) {
                float s1 = 0.f, s2 = 0.f;
#pragma unroll
                for (int ni = 0; ni < 8; ni++) {
                    int c = wn + ni * 8 + tig * 2;
                    float v0 = acc[mi][ni][hf * 2 + 0];
                    float v1 = acc[mi][ni][hf * 2 + 1];
                    s1 += v0 * attS[c] + v1 * attS[c + 1];
                    s2 += v0 * attD[c] + v1 * attD[c + 1];
                }
                s1 += __shfl_xor_sync(0xffffffffu, s1, 1);
                s1 += __shfl_xor_sync(0xffffffffu, s1, 2);
                s2 += __shfl_xor_sync(0xffffffffu, s2, 1);
                s2 += __shfl_xor_sync(0xffffffffu, s2, 2);
                int r = row0 + wm + mi * 16 + hf * 8 + gid;
                if (tig == 0 && r < M) {
                    atomicAdd(&g_asrc2[r], s1);
                    atomicAdd(&g_adst2[r], s2);
                }
            }
        }
    }
}

// ---------------- fused CSR aggregation: conv1 (warp/node, unroll4) ----------
__global__ void k_agg1(const float* __restrict__ b1) {
    int node = blockIdx.x * 8 + (threadIdx.x >> 5);
    if (node >= NN) return;
    int lane = threadIdx.x & 31;
    int h = lane & 3;
    int beg = g_rowptr[node], end = g_rowptr[node + 1];
    float adst = g_adst1[node * 4 + h];
    float den = 0.f;
    float2 acc[8];
#pragma unroll
    for (int j = 0; j < 8; j++) acc[j] = make_float2(0.f, 0.f);
    int i = beg;
    for (; i + 4 <= end; i += 4) {
        int s0 = g_csrc[i], s1 = g_csrc[i + 1], s2 = g_csrc[i + 2], s3 = g_csrc[i + 3];
        float x0 = g_asrc1[s0 * 4 + h] + adst; x0 = x0 > 0.f ? x0 : 0.2f * x0;
        float x1 = g_asrc1[s1 * 4 + h] + adst; x1 = x1 > 0.f ? x1 : 0.2f * x1;
        float x2 = g_asrc1[s2 * 4 + h] + adst; x2 = x2 > 0.f ? x2 : 0.2f * x2;
        float x3 = g_asrc1[s3 * 4 + h] + adst; x3 = x3 > 0.f ? x3 : 0.2f * x3;
        float w0 = __expf(x0), w1 = __expf(x1), w2 = __expf(x2), w3 = __expf(x3);
        den += (w0 + w1) + (w2 + w3);
        float wa[4], wb[4], wc[4], wd[4];
#pragma unroll
        for (int k = 0; k < 4; k++) {
            wa[k] = __shfl_sync(0xffffffffu, w0, k);
            wb[k] = __shfl_sync(0xffffffffu, w1, k);
            wc[k] = __shfl_sync(0xffffffffu, w2, k);
            wd[k] = __shfl_sync(0xffffffffu, w3, k);
        }
        const __half2* h0 = (const __half2*)(g_h1h + (size_t)s0 * 512);
        const __half2* h1p = (const __half2*)(g_h1h + (size_t)s1 * 512);
        const __half2* h2p = (const __half2*)(g_h1h + (size_t)s2 * 512);
        const __half2* h3p = (const __half2*)(g_h1h + (size_t)s3 * 512);
        __half2 r0[8], r1[8], r2[8], r3[8];
#pragma unroll
        for (int j = 0; j < 8; j++) r0[j] = h0[j * 32 + lane];
#pragma unroll
        for (int j = 0; j < 8; j++) r1[j] = h1p[j * 32 + lane];
#pragma unroll
        for (int j = 0; j < 8; j++) r2[j] = h2p[j * 32 + lane];
#pragma unroll
        for (int j = 0; j < 8; j++) r3[j] = h3p[j * 32 + lane];
#pragma unroll
        for (int j = 0; j < 8; j++) {
            int hh = j >> 1;
            float2 f0 = __half22float2(r0[j]);
            float2 f1 = __half22float2(r1[j]);
            float2 f2 = __half22float2(r2[j]);
            float2 f3 = __half22float2(r3[j]);
            acc[j].x += wa[hh] * f0.x + wb[hh] * f1.x + wc[hh] * f2.x + wd[hh] * f3.x;
            acc[j].y += wa[hh] * f0.y + wb[hh] * f1.y + wc[hh] * f2.y + wd[hh] * f3.y;
        }
    }
    for (; i < end; i++) {
        int s0 = g_csrc[i];
        float x0 = g_asrc1[s0 * 4 + h] + adst;
        x0 = x0 > 0.f ? x0 : 0.2f * x0;
        float w0 = __expf(x0);
        den += w0;
        float wa[4];
#pragma unroll
        for (int k = 0; k < 4; k++) wa[k] = __shfl_sync(0xffffffffu, w0, k);
        const __half2* h0 = (const __half2*)(g_h1h + (size_t)s0 * 512);
#pragma unroll
        for (int j = 0; j < 8; j++) {
            float2 f0 = __half22float2(h0[j * 32 + lane]);
            float ww = wa[j >> 1];
            acc[j].x += ww * f0.x;
            acc[j].y += ww * f0.y;
        }
    }
    __half2* od = (__half2*)(g_out1h + (size_t)node * 512);
#pragma unroll
    for (int j = 0; j < 8; j++) {
        float dh = __shfl_sync(0xffffffffu, den, j >> 1);
        float inv = 1.f / (dh + 1e-16f);
        int c = (j * 32 + lane) * 2;
        float2 bb = *(const float2*)(b1 + c);
        float v0 = acc[j].x * inv + bb.x;
        float v1 = acc[j].y * inv + bb.y;
        v0 = v0 > 0.f ? v0 : expm1f(v0);
        v1 = v1 > 0.f ? v1 : expm1f(v1);
        od[j * 32 + lane] = __floats2half2_rn(v0, v1);
    }
}

// ---------------- fused CSR aggregation: conv2 + global max pool -------------
__global__ void k_agg2(const float* __restrict__ b2, const int* __restrict__ batch) {
    int node = blockIdx.x * 8 + (threadIdx.x >> 5);
    if (node >= NN) return;
    int lane = threadIdx.x & 31;
    int beg = g_rowptr[node], end = g_rowptr[node + 1];
    float adst = g_adst2[node];
    float den = 0.f;
    float2 acc[2];
    acc[0] = make_float2(0.f, 0.f);
    acc[1] = make_float2(0.f, 0.f);
    int i = beg;
    for (; i + 4 <= end; i += 4) {
        int s0 = g_csrc[i], s1 = g_csrc[i + 1], s2 = g_csrc[i + 2], s3 = g_csrc[i + 3];
        float x0 = g_asrc2[s0] + adst; x0 = x0 > 0.f ? x0 : 0.2f * x0;
        float x1 = g_asrc2[s1] + adst; x1 = x1 > 0.f ? x1 : 0.2f * x1;
        float x2 = g_asrc2[s2] + adst; x2 = x2 > 0.f ? x2 : 0.2f * x2;
        float x3 = g_asrc2[s3] + adst; x3 = x3 > 0.f ? x3 : 0.2f * x3;
        float w0 = __expf(x0), w1 = __expf(x1), w2 = __expf(x2), w3 = __expf(x3);
        den += (w0 + w1) + (w2 + w3);
        const __half2* h0 = (const __half2*)(g_h2h + (size_t)s0 * 128);
        const __half2* h1p = (const __half2*)(g_h2h + (size_t)s1 * 128);
        const __half2* h2p = (const __half2*)(g_h2h + (size_t)s2 * 128);
        const __half2* h3p = (const __half2*)(g_h2h + (size_t)s3 * 128);
        __half2 r0[2], r1[2], r2[2], r3[2];
#pragma unroll
        for (int j = 0; j < 2; j++) r0[j] = h0[j * 32 + lane];
#pragma unroll
        for (int j = 0; j < 2; j++) r1[j] = h1p[j * 32 + lane];
#pragma unroll
        for (int j = 0; j < 2; j++) r2[j] = h2p[j * 32 + lane];
#pragma unroll
        for (int j = 0; j < 2; j++) r3[j] = h3p[j * 32 + lane];
#pragma unroll
        for (int j = 0; j < 2; j++) {
            float2 f0 = __half22float2(r0[j]);
            float2 f1 = __half22float2(r1[j]);
            float2 f2 = __half22float2(r2[j]);
            float2 f3 = __half22float2(r3[j]);
            acc[j].x += w0 * f0.x + w1 * f1.x + w2 * f2.x + w3 * f3.x;
            acc[j].y += w0 * f0.y + w1 * f1.y + w2 * f2.y + w3 * f3.y;
        }
    }
    for (; i < end; i++) {
        int s0 = g_csrc[i];
        float x0 = g_asrc2[s0] + adst;
        x0 = x0 > 0.f ? x0 : 0.2f * x0;
        float w0 = __expf(x0);
        den += w0;
        const __half2* h0 = (const __half2*)(g_h2h + (size_t)s0 * 128);
#pragma unroll
        for (int j = 0; j < 2; j++) {
            float2 f0 = __half22float2(h0[j * 32 + lane]);
            acc[j].x += w0 * f0.x;
            acc[j].y += w0 * f0.y;
        }
    }
    float inv = 1.f / (den + 1e-16f);
    int g = batch[node];
    unsigned int* pb = g_pooledu + g * 128;
#pragma unroll
    for (int j = 0; j < 2; j++) {
        int c = (j * 32 + lane) * 2;
        float2 bb = *(const float2*)(b2 + c);
        float v0 = acc[j].x * inv + bb.x;
        float v1 = acc[j].y * inv + bb.y;
        v0 = v0 > 0.f ? v0 : expm1f(v0);
        v1 = v1 > 0.f ? v1 : expm1f(v1);
        atomicMax(&pb[c], fkey(v0));
        atomicMax(&pb[c + 1], fkey(v1));
    }
}

// ---------------- classifier --------------------------------------------------
__global__ void k_cls(const float* __restrict__ Wc1, const float* __restrict__ bc1,
                      const float* __restrict__ Wc2, const float* __restrict__ bc2,
                      float* __restrict__ out) {
    int g = blockIdx.x;
    int t = threadIdx.x;  // 64
    __shared__ float sp[128];
    __shared__ float sh[64];
    sp[t] = finv(g_pooledu[g * 128 + t]);
    sp[t + 64] = finv(g_pooledu[g * 128 + 64 + t]);
    __syncthreads();
    float s = bc1[t];
    for (int k = 0; k < 128; k++) s += sp[k] * Wc1[k * 64 + t];
    sh[t] = fmaxf(s, 0.f);
    __syncthreads();
    if (t < NCLS) {
        float o = bc2[t];
        for (int k = 0; k < 64; k++) o += sh[k] * Wc2[k * NCLS + t];
        out[g * NCLS + t] = o;
    }
}

// ---------------- launch ------------------------------------------------------
extern "C" void kernel_launch(void* const* d_in, const int* in_sizes, int n_in,
                              void* d_out, int out_size) {
    const float* xs    = (const float*)d_in[0];
    const int*   xop   = (const int*)d_in[1];
    const int*   xsrc  = (const int*)d_in[2];
    const int*   xsink = (const int*)d_in[3];
    const int*   xstr  = (const int*)d_in[4];
    const int*   xpay  = (const int*)d_in[5];
    const int*   ei    = (const int*)d_in[6];
    const int*   batch = (const int*)d_in[7];
    const float* eop   = (const float*)d_in[8];
    const float* esrc  = (const float*)d_in[9];
    const float* esink = (const float*)d_in[10];
    const float* estr  = (const float*)d_in[11];
    const float* epay  = (const float*)d_in[12];
    const float* ln_g  = (const float*)d_in[13];
    const float* ln_b  = (const float*)d_in[14];
    const float* W1    = (const float*)d_in[15];
    const float* as1   = (const float*)d_in[16];
    const float* ad1   = (const float*)d_in[17];
    const float* b1    = (const float*)d_in[18];
    const float* W2    = (const float*)d_in[19];
    const float* as2   = (const float*)d_in[20];
    const float* ad2   = (const float*)d_in[21];
    const float* b2    = (const float*)d_in[22];
    const float* Wc1   = (const float*)d_in[23];
    const float* bc1   = (const float*)d_in[24];
    const float* Wc2   = (const float*)d_in[25];
    const float* bc2   = (const float*)d_in[26];
    float* out = (float*)d_out;

    __half *p_featsh, *p_h1h, *p_out1h, *p_h2h;
    cudaGetSymbolAddress((void**)&p_featsh, g_featsh);
    cudaGetSymbolAddress((void**)&p_h1h, g_h1h);
    cudaGetSymbolAddress((void**)&p_out1h, g_out1h);
    cudaGetSymbolAddress((void**)&p_h2h, g_h2h);

    int eb = (ET + 255) / 256;
    int nwb = (NN + 7) / 8;  // warp-per-node blocks (256 thr)

    // fused init
    k_init<<<(NN + 255) / 256, 256>>>(W1, as1, ad1);
    // CSR build
    k_deg<<<eb, 256>>>(ei);
    k_scan<<<1, 1024>>>();
    k_fill<<<eb, 256>>>(ei);

    // features (+ fused conv1 logits)
    k_feats<<<NN, 256>>>(xs, xop, xsrc, xsink, xstr, xpay,
                         eop, esrc, esink, estr, epay, ln_g, ln_b);

    // conv1
    {
        dim3 grid(512 / 128, (NN + 127) / 128);
        k_hgemm<<<grid, 256>>>(p_featsh, W1, p_h1h, NN, 512, 256, nullptr, nullptr);
    }
    k_agg1<<<nwb, 256>>>(b1);

    // conv2 (GEMM + fused att2 logits epilogue)
    {
        dim3 grid(1, (NN + 127) / 128);
        k_hgemm<<<grid, 256>>>(p_out1h, W2, p_h2h, NN, 128, 512, as2, ad2);
    }
    k_agg2<<<nwb, 256>>>(b2, batch);

    // classify
    k_cls<<<GG, 64>>>(Wc1, bc1, Wc2, bc2, out);
}

// round 11
// speedup vs baseline: 1.0741x; 1.0741x over previous
#include <cuda_runtime.h>
#include <cuda_fp16.h>
#include <math.h>
#include <stdint.h>

#define NN 50000
#define EE 500000
#define ET (EE + NN)
#define GG 64
#define SCAL 96
#define DD 32
#define INDIM 256
#define CC 128
#define H1N 4
#define NCLS 5

// ---------------- scratch (device globals; no allocation allowed) ----------
__device__ __half g_featsh[NN * INDIM];      // [N,256] fp16
__device__ __half g_h1h[NN * H1N * CC];      // [N,512] fp16
__device__ __half g_out1h[NN * H1N * CC];    // [N,512] fp16
__device__ __half g_h2h[NN * CC];            // [N,128] fp16
__device__ float  g_out2[NN * CC];           // [N,128] fp32 (feeds pool)
__device__ float  g_asrc1[NN * H1N];
__device__ float  g_adst1[NN * H1N];
__device__ float  g_asrc2[NN];
__device__ float  g_adst2[NN];
__device__ float  g_pooled[GG * CC];
__device__ float  g_P1[INDIM * 8];           // [k][j]  j = h*2 + (0:src,1:dst)
// CSR scratch
__device__ int g_deg[NN];
__device__ int g_rowptr[NN + 1];
__device__ int g_cursor[NN];
__device__ int g_csrc[ET];

__device__ __forceinline__ void atomicMaxF(float* addr, float val) {
    int* ia = (int*)addr;
    int old = *ia;
    while (__int_as_float(old) < val) {
        int assumed = old;
        old = atomicCAS(ia, assumed, __float_as_int(val));
        if (old == assumed) break;
    }
}

// ---------------- fused init: zero deg, init pooled, prep1 ------------------
__global__ void k_init(const float* __restrict__ W1, const float* __restrict__ as1,
                       const float* __restrict__ ad1) {
    int idx = blockIdx.x * 256 + threadIdx.x;
    if (idx < NN) g_deg[idx] = 0;
    if (idx < GG * CC) g_pooled[idx] = -3.0e38f;
    if (idx < 2048) {
        int kk = idx >> 3, j = idx & 7, h = j >> 1;
        const float* av = (j & 1) ? ad1 : as1;
        float s = 0.f;
        for (int c = 0; c < 128; c++) s += W1[kk * 512 + h * 128 + c] * av[h * 128 + c];
        g_P1[kk * 8 + j] = s;
    }
}

// ---------------- CSR build -------------------------------------------------
__global__ void k_deg(const int* __restrict__ ei) {
    int e = blockIdx.x * blockDim.x + threadIdx.x;
    if (e >= ET) return;
    int d = (e < EE) ? ei[EE + e] : (e - EE);
    atomicAdd(&g_deg[d], 1);
}

// single block, 1024 threads = 32 warps, coalesced two-phase scan
__global__ void k_scan() {
    __shared__ int wsum[32], wbase[32];
    int t = threadIdx.x, w = t >> 5, lane = t & 31;
    const int CHUNK = 1568;
    int start = w * CHUNK;
    int lim = start + CHUNK; if (lim > NN) lim = NN;
    int s = 0;
    for (int i = start + lane; i < lim; i += 32) s += g_deg[i];
#pragma unroll
    for (int o = 16; o; o >>= 1) s += __shfl_xor_sync(0xffffffffu, s, o);
    if (lane == 0) wsum[w] = s;
    __syncthreads();
    if (w == 0) {
        int v = wsum[lane];
        int incl = v;
#pragma unroll
        for (int o = 1; o < 32; o <<= 1) {
            int u = __shfl_up_sync(0xffffffffu, incl, o);
            if (lane >= o) incl += u;
        }
        wbase[lane] = incl - v;
        if (lane == 31) g_rowptr[NN] = incl;
    }
    __syncthreads();
    int running = wbase[w];
    for (int i0 = start; i0 < lim; i0 += 32) {
        int idx = i0 + lane;
        int v = (idx < lim) ? g_deg[idx] : 0;
        int incl = v;
#pragma unroll
        for (int o = 1; o < 32; o <<= 1) {
            int u = __shfl_up_sync(0xffffffffu, incl, o);
            if (lane >= o) incl += u;
        }
        int excl = incl - v;
        if (idx < lim) { g_rowptr[idx] = running + excl; g_cursor[idx] = running + excl; }
        running += __shfl_sync(0xffffffffu, incl, 31);
    }
}

__global__ void k_fill(const int* __restrict__ ei) {
    int e = blockIdx.x * blockDim.x + threadIdx.x;
    if (e >= ET) return;
    int s, d;
    if (e < EE) { s = ei[e]; d = ei[EE + e]; } else { s = d = e - EE; }
    int pos = atomicAdd(&g_cursor[d], 1);
    g_csrc[pos] = s;
}

// ---------------- feature build + LN + fused conv1 attention logits ---------
__global__ void k_feats(const float* __restrict__ xs,
                        const int* __restrict__ xop, const int* __restrict__ xsrc,
                        const int* __restrict__ xsink, const int* __restrict__ xstr,
                        const int* __restrict__ xpay,
                        const float* __restrict__ eop, const float* __restrict__ esrc,
                        const float* __restrict__ esink, const float* __restrict__ estr,
                        const float* __restrict__ epay,
                        const float* __restrict__ ln_g, const float* __restrict__ ln_b) {
    int n = blockIdx.x;
    int t = threadIdx.x;  // 256 threads
    int w = t >> 5, lane = t & 31;
    float v;
    if (t < SCAL) {
        v = xs[n * SCAL + t];
    } else {
        int grp = (t - SCAL) / DD;
        int d = (t - SCAL) % DD;
        const int* idxp; const float* tab; int L;
        switch (grp) {
            case 0: idxp = xop + n * 16; tab = eop; L = 16; break;
            case 1: idxp = xsrc + n * 8; tab = esrc; L = 8; break;
            case 2: idxp = xsink + n * 8; tab = esink; L = 8; break;
            case 3: idxp = xstr + n * 8; tab = estr; L = 8; break;
            default: idxp = xpay + n * 8; tab = epay; L = 8; break;
        }
        float s = 0.f, cnt = 0.f;
        for (int l = 0; l < L; l++) {
            int id = idxp[l];
            if (id != 0) { s += tab[id * DD + d]; cnt += 1.f; }
        }
        v = s / (cnt + 1e-9f);
    }
    __shared__ float smA[8], smB[8];
    __shared__ float sm8[8][8];
    float s1 = v, s2 = v * v;
#pragma unroll
    for (int o = 16; o; o >>= 1) {
        s1 += __shfl_xor_sync(0xffffffffu, s1, o);
        s2 += __shfl_xor_sync(0xffffffffu, s2, o);
    }
    if (lane == 0) { smA[w] = s1; smB[w] = s2; }
    __syncthreads();
    float S = 0.f, S2 = 0.f;
#pragma unroll
    for (int i = 0; i < 8; i++) { S += smA[i]; S2 += smB[i]; }
    float mu = S * (1.f / 256.f);
    float var = S2 * (1.f / 256.f) - mu * mu;
    float o = (v - mu) * rsqrtf(var + 1e-5f) * ln_g[t] + ln_b[t];
    g_featsh[n * INDIM + t] = __float2half_rn(o);
    float pj[8];
#pragma unroll
    for (int j = 0; j < 8; j++) pj[j] = o * g_P1[t * 8 + j];
#pragma unroll
    for (int j = 0; j < 8; j++)
#pragma unroll
        for (int off = 16; off; off >>= 1) pj[j] += __shfl_xor_sync(0xffffffffu, pj[j], off);
    if (lane == 0) {
#pragma unroll
        for (int j = 0; j < 8; j++) sm8[w][j] = pj[j];
    }
    __syncthreads();
    if (t < 8) {
        float s = 0.f;
#pragma unroll
        for (int i = 0; i < 8; i++) s += sm8[i][t];
        int h = t >> 1;
        if (t & 1) g_adst1[n * 4 + h] = s;
        else       g_asrc1[n * 4 + h] = s;
    }
}

// ---------------- fp16 tensor-core GEMM: C[M,N]=A[M,K]@B[K,N] ---------------
#define MMA_F16(d0,d1,d2,d3,a0,a1,a2,a3,b0,b1) \
    asm volatile("mma.sync.aligned.m16n8k16.row.col.f32.f16.f16.f32 " \
                 "{%0,%1,%2,%3},{%4,%5,%6,%7},{%8,%9},{%0,%1,%2,%3};" \
                 : "+f"(d0), "+f"(d1), "+f"(d2), "+f"(d3) \
                 : "r"(a0), "r"(a1), "r"(a2), "r"(a3), "r"(b0), "r"(b1))

__device__ __forceinline__ uint32_t pack_h2(float x, float y) {
    __half2 h = __floats2half2_rn(x, y);
    return *(uint32_t*)&h;
}

__global__ void __launch_bounds__(256) k_hgemm(const __half* __restrict__ A,
                                               const float* __restrict__ B,
                                               __half* __restrict__ C, int M, int N, int K) {
    __shared__ uint32_t As2[2][128][20];
    __shared__ uint32_t Bs2[2][128][20];
    int tid = threadIdx.x;
    int wid = tid >> 5, lane = tid & 31;
    int wm = (wid & 3) * 32;
    int wn = (wid >> 2) * 64;
    int gid = lane >> 2, tig = lane & 3;
    int row0 = blockIdx.y * 128, col0 = blockIdx.x * 128;
    float acc[2][8][4];
#pragma unroll
    for (int i = 0; i < 2; i++)
#pragma unroll
        for (int j = 0; j < 8; j++)
#pragma unroll
            for (int q = 0; q < 4; q++) acc[i][j][q] = 0.f;

    int T = K >> 5;
    {
#pragma unroll
        for (int r = 0; r < 8; r++) {
            int u = tid + 256 * r;
            int m = u >> 4, q = u & 15;
            int gm = row0 + m;
            As2[0][m][q] = (gm < M) ? ((const uint32_t*)(A + (size_t)gm * K))[q] : 0u;
        }
#pragma unroll
        for (int r = 0; r < 8; r++) {
            int u = tid + 256 * r;
            int n = u & 127, q = u >> 7;
            float b0v = B[(size_t)(2 * q) * N + col0 + n];
            float b1v = B[(size_t)(2 * q + 1) * N + col0 + n];
            Bs2[0][n][q] = pack_h2(b0v, b1v);
        }
    }
    __syncthreads();

    for (int t = 0; t < T; t++) {
        int cur = t & 1;
        uint32_t ra[8], rb[8];
        if (t + 1 < T) {
            int k0 = (t + 1) << 5;
#pragma unroll
            for (int r = 0; r < 8; r++) {
                int u = tid + 256 * r;
                int m = u >> 4, q = u & 15;
                int gm = row0 + m;
                ra[r] = (gm < M) ? ((const uint32_t*)(A + (size_t)gm * K + k0))[q] : 0u;
            }
#pragma unroll
            for (int r = 0; r < 8; r++) {
                int u = tid + 256 * r;
                int n = u & 127, q = u >> 7;
                float b0v = B[(size_t)(k0 + 2 * q) * N + col0 + n];
                float b1v = B[(size_t)(k0 + 2 * q + 1) * N + col0 + n];
                rb[r] = pack_h2(b0v, b1v);
            }
        }
#pragma unroll
        for (int ks = 0; ks < 2; ks++) {
            int kb = ks * 8;
            uint32_t a[2][4];
#pragma unroll
            for (int mi = 0; mi < 2; mi++) {
                int r = wm + mi * 16 + gid;
                a[mi][0] = As2[cur][r][kb + tig];
                a[mi][1] = As2[cur][r + 8][kb + tig];
                a[mi][2] = As2[cur][r][kb + tig + 4];
                a[mi][3] = As2[cur][r + 8][kb + tig + 4];
            }
#pragma unroll
            for (int ni = 0; ni < 8; ni++) {
                uint32_t b0 = Bs2[cur][wn + ni * 8 + gid][kb + tig];
                uint32_t b1 = Bs2[cur][wn + ni * 8 + gid][kb + tig + 4];
#pragma unroll
                for (int mi = 0; mi < 2; mi++) {
                    MMA_F16(acc[mi][ni][0], acc[mi][ni][1], acc[mi][ni][2], acc[mi][ni][3],
                            a[mi][0], a[mi][1], a[mi][2], a[mi][3], b0, b1);
                }
            }
        }
        if (t + 1 < T) {
            int nxt = 1 - cur;
#pragma unroll
            for (int r = 0; r < 8; r++) {
                int u = tid + 256 * r;
                int m = u >> 4, q = u & 15;
                As2[nxt][m][q] = ra[r];
            }
#pragma unroll
            for (int r = 0; r < 8; r++) {
                int u = tid + 256 * r;
                int n = u & 127, q = u >> 7;
                Bs2[nxt][n][q] = rb[r];
            }
        }
        __syncthreads();
    }
#pragma unroll
    for (int mi = 0; mi < 2; mi++) {
#pragma unroll
        for (int ni = 0; ni < 8; ni++) {
            int r = row0 + wm + mi * 16 + gid;
            int c = col0 + wn + ni * 8 + tig * 2;
            if (r < M)
                *(__half2*)(C + (size_t)r * N + c) = __floats2half2_rn(acc[mi][ni][0], acc[mi][ni][1]);
            if (r + 8 < M)
                *(__half2*)(C + (size_t)(r + 8) * N + c) = __floats2half2_rn(acc[mi][ni][2], acc[mi][ni][3]);
        }
    }
}

// ---------------- conv2 attention logits (reads fp16 h2) --------------------
__global__ void k_att2(const float* __restrict__ as2, const float* __restrict__ ad2) {
    int n = blockIdx.x * 8 + (threadIdx.x >> 5);
    if (n >= NN) return;
    int lane = threadIdx.x & 31;
    const __half2* hrow = (const __half2*)(g_h2h + (size_t)n * 128);
    float s1 = 0.f, s2 = 0.f;
#pragma unroll
    for (int j = 0; j < 2; j++) {
        float2 hv = __half22float2(hrow[j * 32 + lane]);
        int c = (j * 32 + lane) * 2;
        s1 += hv.x * as2[c] + hv.y * as2[c + 1];
        s2 += hv.x * ad2[c] + hv.y * ad2[c + 1];
    }
    for (int o = 16; o; o >>= 1) {
        s1 += __shfl_down_sync(0xffffffffu, s1, o);
        s2 += __shfl_down_sync(0xffffffffu, s2, o);
    }
    if (lane == 0) { g_asrc2[n] = s1; g_adst2[n] = s2; }
}

// helper: acc[0..7] += w * (8 halves in uint4)
__device__ __forceinline__ void acc8(float* acc, uint4 u, float w) {
    float2 f;
    f = __half22float2(*(__half2*)&u.x); acc[0] += w * f.x; acc[1] += w * f.y;
    f = __half22float2(*(__half2*)&u.y); acc[2] += w * f.x; acc[3] += w * f.y;
    f = __half22float2(*(__half2*)&u.z); acc[4] += w * f.x; acc[5] += w * f.y;
    f = __half22float2(*(__half2*)&u.w); acc[6] += w * f.x; acc[7] += w * f.y;
}

// ---------------- fused CSR aggregation: conv1 (warp/node, LDG.128 gathers) --
// lane owns channels [8*lane, 8*lane+8) (head lane>>4) and [256+8*lane, ...) (head 2+lane>>4)
__global__ void k_agg1(const float* __restrict__ b1) {
    int node = blockIdx.x * 8 + (threadIdx.x >> 5);
    if (node >= NN) return;
    int lane = threadIdx.x & 31;
    int h = lane & 3;
    int headA = lane >> 4;       // 0 or 1
    int headB = 2 + headA;       // 2 or 3
    int beg = g_rowptr[node], end = g_rowptr[node + 1];
    float adst = g_adst1[node * 4 + h];
    float den = 0.f;
    float accA[8], accB[8];
#pragma unroll
    for (int k = 0; k < 8; k++) { accA[k] = 0.f; accB[k] = 0.f; }
    int i = beg;
    for (; i + 2 <= end; i += 2) {
        int s0 = g_csrc[i], s1 = g_csrc[i + 1];
        float x0 = g_asrc1[s0 * 4 + h] + adst; x0 = x0 > 0.f ? x0 : 0.2f * x0;
        float x1 = g_asrc1[s1 * 4 + h] + adst; x1 = x1 > 0.f ? x1 : 0.2f * x1;
        float w0 = __expf(x0), w1 = __expf(x1);
        den += w0 + w1;
        float wA0 = __shfl_sync(0xffffffffu, w0, headA);
        float wB0 = __shfl_sync(0xffffffffu, w0, headB);
        float wA1 = __shfl_sync(0xffffffffu, w1, headA);
        float wB1 = __shfl_sync(0xffffffffu, w1, headB);
        const uint4* p0 = (const uint4*)(g_h1h + (size_t)s0 * 512);
        const uint4* p1 = (const uint4*)(g_h1h + (size_t)s1 * 512);
        uint4 A0 = p0[lane], B0 = p0[32 + lane];
        uint4 A1 = p1[lane], B1 = p1[32 + lane];
        acc8(accA, A0, wA0); acc8(accB, B0, wB0);
        acc8(accA, A1, wA1); acc8(accB, B1, wB1);
    }
    if (i < end) {
        int s0 = g_csrc[i];
        float x0 = g_asrc1[s0 * 4 + h] + adst; x0 = x0 > 0.f ? x0 : 0.2f * x0;
        float w0 = __expf(x0);
        den += w0;
        float wA0 = __shfl_sync(0xffffffffu, w0, headA);
        float wB0 = __shfl_sync(0xffffffffu, w0, headB);
        const uint4* p0 = (const uint4*)(g_h1h + (size_t)s0 * 512);
        uint4 A0 = p0[lane], B0 = p0[32 + lane];
        acc8(accA, A0, wA0); acc8(accB, B0, wB0);
    }
    float dhA = __shfl_sync(0xffffffffu, den, headA);
    float dhB = __shfl_sync(0xffffffffu, den, headB);
    float invA = 1.f / (dhA + 1e-16f);
    float invB = 1.f / (dhB + 1e-16f);
    const float4* bp = (const float4*)b1;
    float4 bA0 = bp[2 * lane], bA1 = bp[2 * lane + 1];
    float4 bB0 = bp[64 + 2 * lane], bB1 = bp[64 + 2 * lane + 1];
    float vA[8], vB[8];
    vA[0] = accA[0] * invA + bA0.x; vA[1] = accA[1] * invA + bA0.y;
    vA[2] = accA[2] * invA + bA0.z; vA[3] = accA[3] * invA + bA0.w;
    vA[4] = accA[4] * invA + bA1.x; vA[5] = accA[5] * invA + bA1.y;
    vA[6] = accA[6] * invA + bA1.z; vA[7] = accA[7] * invA + bA1.w;
    vB[0] = accB[0] * invB + bB0.x; vB[1] = accB[1] * invB + bB0.y;
    vB[2] = accB[2] * invB + bB0.z; vB[3] = accB[3] * invB + bB0.w;
    vB[4] = accB[4] * invB + bB1.x; vB[5] = accB[5] * invB + bB1.y;
    vB[6] = accB[6] * invB + bB1.z; vB[7] = accB[7] * invB + bB1.w;
#pragma unroll
    for (int k = 0; k < 8; k++) {
        vA[k] = vA[k] > 0.f ? vA[k] : expm1f(vA[k]);
        vB[k] = vB[k] > 0.f ? vB[k] : expm1f(vB[k]);
    }
    uint4 oA, oB;
    oA.x = pack_h2(vA[0], vA[1]); oA.y = pack_h2(vA[2], vA[3]);
    oA.z = pack_h2(vA[4], vA[5]); oA.w = pack_h2(vA[6], vA[7]);
    oB.x = pack_h2(vB[0], vB[1]); oB.y = pack_h2(vB[2], vB[3]);
    oB.z = pack_h2(vB[4], vB[5]); oB.w = pack_h2(vB[6], vB[7]);
    uint4* od = (uint4*)(g_out1h + (size_t)node * 512);
    od[lane] = oA;
    od[32 + lane] = oB;
}

// ---------------- fused CSR aggregation: conv2 (warp/node, LDG.64 gathers) ---
// lane owns channels [4*lane, 4*lane+4)
__global__ void k_agg2(const float* __restrict__ b2) {
    int node = blockIdx.x * 8 + (threadIdx.x >> 5);
    if (node >= NN) return;
    int lane = threadIdx.x & 31;
    int beg = g_rowptr[node], end = g_rowptr[node + 1];
    float adst = g_adst2[node];
    float den = 0.f;
    float acc[4] = {0.f, 0.f, 0.f, 0.f};
    int i = beg;
    for (; i + 2 <= end; i += 2) {
        int s0 = g_csrc[i], s1 = g_csrc[i + 1];
        float x0 = g_asrc2[s0] + adst; x0 = x0 > 0.f ? x0 : 0.2f * x0;
        float x1 = g_asrc2[s1] + adst; x1 = x1 > 0.f ? x1 : 0.2f * x1;
        float w0 = __expf(x0), w1 = __expf(x1);
        den += w0 + w1;
        uint2 U0 = ((const uint2*)(g_h2h + (size_t)s0 * 128))[lane];
        uint2 U1 = ((const uint2*)(g_h2h + (size_t)s1 * 128))[lane];
        float2 f;
        f = __half22float2(*(__half2*)&U0.x); acc[0] += w0 * f.x; acc[1] += w0 * f.y;
        f = __half22float2(*(__half2*)&U0.y); acc[2] += w0 * f.x; acc[3] += w0 * f.y;
        f = __half22float2(*(__half2*)&U1.x); acc[0] += w1 * f.x; acc[1] += w1 * f.y;
        f = __half22float2(*(__half2*)&U1.y); acc[2] += w1 * f.x; acc[3] += w1 * f.y;
    }
    if (i < end) {
        int s0 = g_csrc[i];
        float x0 = g_asrc2[s0] + adst; x0 = x0 > 0.f ? x0 : 0.2f * x0;
        float w0 = __expf(x0);
        den += w0;
        uint2 U0 = ((const uint2*)(g_h2h + (size_t)s0 * 128))[lane];
        float2 f;
        f = __half22float2(*(__half2*)&U0.x); acc[0] += w0 * f.x; acc[1] += w0 * f.y;
        f = __half22float2(*(__half2*)&U0.y); acc[2] += w0 * f.x; acc[3] += w0 * f.y;
    }
    float inv = 1.f / (den + 1e-16f);
    float4 bb = ((const float4*)b2)[lane];
    float v0 = acc[0] * inv + bb.x;
    float v1 = acc[1] * inv + bb.y;
    float v2 = acc[2] * inv + bb.z;
    float v3 = acc[3] * inv + bb.w;
    v0 = v0 > 0.f ? v0 : expm1f(v0);
    v1 = v1 > 0.f ? v1 : expm1f(v1);
    v2 = v2 > 0.f ? v2 : expm1f(v2);
    v3 = v3 > 0.f ? v3 : expm1f(v3);
    ((float4*)(g_out2 + (size_t)node * 128))[lane] = make_float4(v0, v1, v2, v3);
}

// ---------------- global max pool (parallel, segment flush) ------------------
__global__ void k_pool(const int* __restrict__ batch) {
    int base = blockIdx.x * 128;
    int c = threadIdx.x;  // 128
    int lim = base + 128; if (lim > NN) lim = NN;
    int curg = batch[base];
    float mx = -3.4e38f;
    for (int n = base; n < lim; n++) {
        int g = batch[n];
        if (g != curg) {
            atomicMaxF(&g_pooled[curg * 128 + c], mx);
            curg = g;
            mx = -3.4e38f;
        }
        mx = fmaxf(mx, g_out2[(size_t)n * 128 + c]);
    }
    atomicMaxF(&g_pooled[curg * 128 + c], mx);
}

// ---------------- classifier --------------------------------------------------
__global__ void k_cls(const float* __restrict__ Wc1, const float* __restrict__ bc1,
                      const float* __restrict__ Wc2, const float* __restrict__ bc2,
                      float* __restrict__ out) {
    int g = blockIdx.x;
    int t = threadIdx.x;  // 64
    __shared__ float sp[128];
    __shared__ float sh[64];
    sp[t] = g_pooled[g * 128 + t];
    sp[t + 64] = g_pooled[g * 128 + 64 + t];
    __syncthreads();
    float s = bc1[t];
    for (int k = 0; k < 128; k++) s += sp[k] * Wc1[k * 64 + t];
    sh[t] = fmaxf(s, 0.f);
    __syncthreads();
    if (t < NCLS) {
        float o = bc2[t];
        for (int k = 0; k < 64; k++) o += sh[k] * Wc2[k * NCLS + t];
        out[g * NCLS + t] = o;
    }
}

// ---------------- launch ------------------------------------------------------
extern "C" void kernel_launch(void* const* d_in, const int* in_sizes, int n_in,
                              void* d_out, int out_size) {
    const float* xs    = (const float*)d_in[0];
    const int*   xop   = (const int*)d_in[1];
    const int*   xsrc  = (const int*)d_in[2];
    const int*   xsink = (const int*)d_in[3];
    const int*   xstr  = (const int*)d_in[4];
    const int*   xpay  = (const int*)d_in[5];
    const int*   ei    = (const int*)d_in[6];
    const int*   batch = (const int*)d_in[7];
    const float* eop   = (const float*)d_in[8];
    const float* esrc  = (const float*)d_in[9];
    const float* esink = (const float*)d_in[10];
    const float* estr  = (const float*)d_in[11];
    const float* epay  = (const float*)d_in[12];
    const float* ln_g  = (const float*)d_in[13];
    const float* ln_b  = (const float*)d_in[14];
    const float* W1    = (const float*)d_in[15];
    const float* as1   = (const float*)d_in[16];
    const float* ad1   = (const float*)d_in[17];
    const float* b1    = (const float*)d_in[18];
    const float* W2    = (const float*)d_in[19];
    const float* as2   = (const float*)d_in[20];
    const float* ad2   = (const float*)d_in[21];
    const float* b2    = (const float*)d_in[22];
    const float* Wc1   = (const float*)d_in[23];
    const float* bc1   = (const float*)d_in[24];
    const float* Wc2   = (const float*)d_in[25];
    const float* bc2   = (const float*)d_in[26];
    float* out = (float*)d_out;

    __half *p_featsh, *p_h1h, *p_out1h, *p_h2h;
    cudaGetSymbolAddress((void**)&p_featsh, g_featsh);
    cudaGetSymbolAddress((void**)&p_h1h, g_h1h);
    cudaGetSymbolAddress((void**)&p_out1h, g_out1h);
    cudaGetSymbolAddress((void**)&p_h2h, g_h2h);

    int eb = (ET + 255) / 256;
    int nwb = (NN + 7) / 8;  // warp-per-node blocks (256 thr)

    // fused init
    k_init<<<(NN + 255) / 256, 256>>>(W1, as1, ad1);
    // CSR build
    k_deg<<<eb, 256>>>(ei);
    k_scan<<<1, 1024>>>();
    k_fill<<<eb, 256>>>(ei);

    // features (+ fused conv1 logits)
    k_feats<<<NN, 256>>>(xs, xop, xsrc, xsink, xstr, xpay,
                         eop, esrc, esink, estr, epay, ln_g, ln_b);

    // conv1
    {
        dim3 grid(512 / 128, (NN + 127) / 128);
        k_hgemm<<<grid, 256>>>(p_featsh, W1, p_h1h, NN, 512, 256);
    }
    k_agg1<<<nwb, 256>>>(b1);

    // conv2
    {
        dim3 grid(1, (NN + 127) / 128);
        k_hgemm<<<grid, 256>>>(p_out1h, W2, p_h2h, NN, 128, 512);
    }
    k_att2<<<nwb, 256>>>(as2, ad2);
    k_agg2<<<nwb, 256>>>(b2);

    // pool + classify
    k_pool<<<(NN + 127) / 128, 128>>>(batch);
    k_cls<<<GG, 64>>>(Wc1, bc1, Wc2, bc2, out);
}

// round 14
// speedup vs baseline: 1.3543x; 1.2608x over previous
#include <cuda_runtime.h>
#include <cuda_fp16.h>
#include <math.h>
#include <stdint.h>

#define NN 50000
#define EE 500000
#define ET (EE + NN)
#define GG 64
#define SCAL 96
#define DD 32
#define INDIM 256
#define CC 128
#define H1N 4
#define NCLS 5

// ---------------- scratch (device globals; no allocation allowed) ----------
__device__ __half g_featsh[NN * INDIM];      // [N,256] fp16
__device__ __half g_h1h[NN * H1N * CC];      // [N,512] fp16
__device__ __half g_out1h[NN * H1N * CC];    // [N,512] fp16
__device__ __half g_h2h[NN * CC];            // [N,128] fp16
__device__ float  g_out2[NN * CC];           // [N,128] fp32 (feeds pool)
__device__ float  g_asrc1[NN * H1N];
__device__ float  g_adst1[NN * H1N];
__device__ float  g_asrc2[NN];
__device__ float  g_adst2[NN];
__device__ float  g_pooled[GG * CC];
__device__ float  g_P1T[8 * INDIM];          // [j][k]  j = h*2 + (0:src,1:dst)
// CSR scratch
__device__ int g_deg[NN];
__device__ int g_rowptr[NN + 1];
__device__ int g_cursor[NN];
__device__ int g_csrc[ET];

__device__ __forceinline__ void atomicMaxF(float* addr, float val) {
    int* ia = (int*)addr;
    int old = *ia;
    while (__int_as_float(old) < val) {
        int assumed = old;
        old = atomicCAS(ia, assumed, __float_as_int(val));
        if (old == assumed) break;
    }
}

// ---------------- init kernels ----------------------------------------------
__global__ void k_zerodeg() {
    int i = blockIdx.x * 256 + threadIdx.x;
    if (i < NN) g_deg[i] = 0;
}

// pooled init + P1T prep (main stream; small)
__global__ void k_init(const float* __restrict__ W1, const float* __restrict__ as1,
                       const float* __restrict__ ad1) {
    int idx = blockIdx.x * 256 + threadIdx.x;  // grid 32 -> 8192
    if (idx < GG * CC) g_pooled[idx] = -3.0e38f;
    if (idx < 2048) {
        int j = idx >> 8, kk = idx & 255;
        int h = j >> 1;
        const float* av = (j & 1) ? ad1 : as1;
        float s = 0.f;
        for (int c = 0; c < 128; c++) s += W1[kk * 512 + h * 128 + c] * av[h * 128 + c];
        g_P1T[j * 256 + kk] = s;
    }
}

// ---------------- CSR build (side stream) ------------------------------------
__global__ void k_deg(const int* __restrict__ ei) {
    int e = blockIdx.x * blockDim.x + threadIdx.x;
    if (e >= ET) return;
    int d = (e < EE) ? ei[EE + e] : (e - EE);
    atomicAdd(&g_deg[d], 1);
}

// single block, 1024 threads = 32 warps, coalesced two-phase scan
__global__ void k_scan() {
    __shared__ int wsum[32], wbase[32];
    int t = threadIdx.x, w = t >> 5, lane = t & 31;
    const int CHUNK = 1568;
    int start = w * CHUNK;
    int lim = start + CHUNK; if (lim > NN) lim = NN;
    int s = 0;
    for (int i = start + lane; i < lim; i += 32) s += g_deg[i];
#pragma unroll
    for (int o = 16; o; o >>= 1) s += __shfl_xor_sync(0xffffffffu, s, o);
    if (lane == 0) wsum[w] = s;
    __syncthreads();
    if (w == 0) {
        int v = wsum[lane];
        int incl = v;
#pragma unroll
        for (int o = 1; o < 32; o <<= 1) {
            int u = __shfl_up_sync(0xffffffffu, incl, o);
            if (lane >= o) incl += u;
        }
        wbase[lane] = incl - v;
        if (lane == 31) g_rowptr[NN] = incl;
    }
    __syncthreads();
    int running = wbase[w];
    for (int i0 = start; i0 < lim; i0 += 32) {
        int idx = i0 + lane;
        int v = (idx < lim) ? g_deg[idx] : 0;
        int incl = v;
#pragma unroll
        for (int o = 1; o < 32; o <<= 1) {
            int u = __shfl_up_sync(0xffffffffu, incl, o);
            if (lane >= o) incl += u;
        }
        int excl = incl - v;
        if (idx < lim) { g_rowptr[idx] = running + excl; g_cursor[idx] = running + excl; }
        running += __shfl_sync(0xffffffffu, incl, 31);
    }
}

__global__ void k_fill(const int* __restrict__ ei) {
    int e = blockIdx.x * blockDim.x + threadIdx.x;
    if (e >= ET) return;
    int s, d;
    if (e < EE) { s = ei[e]; d = ei[EE + e]; } else { s = d = e - EE; }
    int pos = atomicAdd(&g_cursor[d], 1);
    g_csrc[pos] = s;
}

// ---------------- feature build + LN + fused conv1 attention logits ---------
__global__ void k_feats(const float* __restrict__ xs,
                        const int* __restrict__ xop, const int* __restrict__ xsrc,
                        const int* __restrict__ xsink, const int* __restrict__ xstr,
                        const int* __restrict__ xpay,
                        const float* __restrict__ eop, const float* __restrict__ esrc,
                        const float* __restrict__ esink, const float* __restrict__ estr,
                        const float* __restrict__ epay,
                        const float* __restrict__ ln_g, const float* __restrict__ ln_b) {
    int n = blockIdx.x;
    int t = threadIdx.x;  // 256 threads
    int w = t >> 5, lane = t & 31;
    float v;
    if (t < SCAL) {
        v = xs[n * SCAL + t];
    } else {
        int grp = (t - SCAL) / DD;
        int d = (t - SCAL) % DD;
        const int* idxp; const float* tab; int L;
        switch (grp) {
            case 0: idxp = xop + n * 16; tab = eop; L = 16; break;
            case 1: idxp = xsrc + n * 8; tab = esrc; L = 8; break;
            case 2: idxp = xsink + n * 8; tab = esink; L = 8; break;
            case 3: idxp = xstr + n * 8; tab = estr; L = 8; break;
            default: idxp = xpay + n * 8; tab = epay; L = 8; break;
        }
        float s = 0.f, cnt = 0.f;
        for (int l = 0; l < L; l++) {
            int id = idxp[l];
            if (id != 0) { s += tab[id * DD + d]; cnt += 1.f; }
        }
        v = s / (cnt + 1e-9f);
    }
    __shared__ float smA[8], smB[8];
    __shared__ float sfeat[256];
    float s1 = v, s2 = v * v;
#pragma unroll
    for (int o = 16; o; o >>= 1) {
        s1 += __shfl_xor_sync(0xffffffffu, s1, o);
        s2 += __shfl_xor_sync(0xffffffffu, s2, o);
    }
    if (lane == 0) { smA[w] = s1; smB[w] = s2; }
    __syncthreads();
    float S = 0.f, S2 = 0.f;
#pragma unroll
    for (int i = 0; i < 8; i++) { S += smA[i]; S2 += smB[i]; }
    float mu = S * (1.f / 256.f);
    float var = S2 * (1.f / 256.f) - mu * mu;
    float o = (v - mu) * rsqrtf(var + 1e-5f) * ln_g[t] + ln_b[t];
    g_featsh[n * INDIM + t] = __float2half_rn(o);
    sfeat[t] = o;
    __syncthreads();
    // warp w computes logit j=w: dot(sfeat, P1T[w])
    float acc = 0.f;
#pragma unroll
    for (int q = 0; q < 8; q++)
        acc += sfeat[q * 32 + lane] * g_P1T[w * 256 + q * 32 + lane];
#pragma unroll
    for (int off = 16; off; off >>= 1) acc += __shfl_xor_sync(0xffffffffu, acc, off);
    if (lane == 0) {
        int h = w >> 1;
        if (w & 1) g_adst1[n * 4 + h] = acc;
        else       g_asrc1[n * 4 + h] = acc;
    }
}

// ---------------- fp16 tensor-core GEMM: C[M,N]=A[M,K]@B[K,N] ---------------
#define MMA_F16(d0,d1,d2,d3,a0,a1,a2,a3,b0,b1) \
    asm volatile("mma.sync.aligned.m16n8k16.row.col.f32.f16.f16.f32 " \
                 "{%0,%1,%2,%3},{%4,%5,%6,%7},{%8,%9},{%0,%1,%2,%3};" \
                 : "+f"(d0), "+f"(d1), "+f"(d2), "+f"(d3) \
                 : "r"(a0), "r"(a1), "r"(a2), "r"(a3), "r"(b0), "r"(b1))

__device__ __forceinline__ uint32_t pack_h2(float x, float y) {
    __half2 h = __floats2half2_rn(x, y);
    return *(uint32_t*)&h;
}

__global__ void __launch_bounds__(256) k_hgemm(const __half* __restrict__ A,
                                               const float* __restrict__ B,
                                               __half* __restrict__ C, int M, int N, int K) {
    __shared__ uint32_t As2[2][128][20];
    __shared__ uint32_t Bs2[2][128][20];
    int tid = threadIdx.x;
    int wid = tid >> 5, lane = tid & 31;
    int wm = (wid & 3) * 32;
    int wn = (wid >> 2) * 64;
    int gid = lane >> 2, tig = lane & 3;
    int row0 = blockIdx.y * 128, col0 = blockIdx.x * 128;
    float acc[2][8][4];
#pragma unroll
    for (int i = 0; i < 2; i++)
#pragma unroll
        for (int j = 0; j < 8; j++)
#pragma unroll
            for (int q = 0; q < 4; q++) acc[i][j][q] = 0.f;

    int T = K >> 5;
    {
#pragma unroll
        for (int r = 0; r < 8; r++) {
            int u = tid + 256 * r;
            int m = u >> 4, q = u & 15;
            int gm = row0 + m;
            As2[0][m][q] = (gm < M) ? ((const uint32_t*)(A + (size_t)gm * K))[q] : 0u;
        }
#pragma unroll
        for (int r = 0; r < 8; r++) {
            int u = tid + 256 * r;
            int n = u & 127, q = u >> 7;
            float b0v = B[(size_t)(2 * q) * N + col0 + n];
            float b1v = B[(size_t)(2 * q + 1) * N + col0 + n];
            Bs2[0][n][q] = pack_h2(b0v, b1v);
        }
    }
    __syncthreads();

    for (int t = 0; t < T; t++) {
        int cur = t & 1;
        uint32_t ra[8], rb[8];
        if (t + 1 < T) {
            int k0 = (t + 1) << 5;
#pragma unroll
            for (int r = 0; r < 8; r++) {
                int u = tid + 256 * r;
                int m = u >> 4, q = u & 15;
                int gm = row0 + m;
                ra[r] = (gm < M) ? ((const uint32_t*)(A + (size_t)gm * K + k0))[q] : 0u;
            }
#pragma unroll
            for (int r = 0; r < 8; r++) {
                int u = tid + 256 * r;
                int n = u & 127, q = u >> 7;
                float b0v = B[(size_t)(k0 + 2 * q) * N + col0 + n];
                float b1v = B[(size_t)(k0 + 2 * q + 1) * N + col0 + n];
                rb[r] = pack_h2(b0v, b1v);
            }
        }
#pragma unroll
        for (int ks = 0; ks < 2; ks++) {
            int kb = ks * 8;
            uint32_t a[2][4];
#pragma unroll
            for (int mi = 0; mi < 2; mi++) {
                int r = wm + mi * 16 + gid;
                a[mi][0] = As2[cur][r][kb + tig];
                a[mi][1] = As2[cur][r + 8][kb + tig];
                a[mi][2] = As2[cur][r][kb + tig + 4];
                a[mi][3] = As2[cur][r + 8][kb + tig + 4];
            }
#pragma unroll
            for (int ni = 0; ni < 8; ni++) {
                uint32_t b0 = Bs2[cur][wn + ni * 8 + gid][kb + tig];
                uint32_t b1 = Bs2[cur][wn + ni * 8 + gid][kb + tig + 4];
#pragma unroll
                for (int mi = 0; mi < 2; mi++) {
                    MMA_F16(acc[mi][ni][0], acc[mi][ni][1], acc[mi][ni][2], acc[mi][ni][3],
                            a[mi][0], a[mi][1], a[mi][2], a[mi][3], b0, b1);
                }
            }
        }
        if (t + 1 < T) {
            int nxt = 1 - cur;
#pragma unroll
            for (int r = 0; r < 8; r++) {
                int u = tid + 256 * r;
                int m = u >> 4, q = u & 15;
                As2[nxt][m][q] = ra[r];
            }
#pragma unroll
            for (int r = 0; r < 8; r++) {
                int u = tid + 256 * r;
                int n = u & 127, q = u >> 7;
                Bs2[nxt][n][q] = rb[r];
            }
        }
        __syncthreads();
    }
#pragma unroll
    for (int mi = 0; mi < 2; mi++) {
#pragma unroll
        for (int ni = 0; ni < 8; ni++) {
            int r = row0 + wm + mi * 16 + gid;
            int c = col0 + wn + ni * 8 + tig * 2;
            if (r < M)
                *(__half2*)(C + (size_t)r * N + c) = __floats2half2_rn(acc[mi][ni][0], acc[mi][ni][1]);
            if (r + 8 < M)
                *(__half2*)(C + (size_t)(r + 8) * N + c) = __floats2half2_rn(acc[mi][ni][2], acc[mi][ni][3]);
        }
    }
}

// ---------------- conv2 attention logits (reads fp16 h2) --------------------
__global__ void k_att2(const float* __restrict__ as2, const float* __restrict__ ad2) {
    int n = blockIdx.x * 8 + (threadIdx.x >> 5);
    if (n >= NN) return;
    int lane = threadIdx.x & 31;
    const __half2* hrow = (const __half2*)(g_h2h + (size_t)n * 128);
    float s1 = 0.f, s2 = 0.f;
#pragma unroll
    for (int j = 0; j < 2; j++) {
        float2 hv = __half22float2(hrow[j * 32 + lane]);
        int c = (j * 32 + lane) * 2;
        s1 += hv.x * as2[c] + hv.y * as2[c + 1];
        s2 += hv.x * ad2[c] + hv.y * ad2[c + 1];
    }
    for (int o = 16; o; o >>= 1) {
        s1 += __shfl_down_sync(0xffffffffu, s1, o);
        s2 += __shfl_down_sync(0xffffffffu, s2, o);
    }
    if (lane == 0) { g_asrc2[n] = s1; g_adst2[n] = s2; }
}

// helper: acc[0..7] += w * (8 halves in uint4)
__device__ __forceinline__ void acc8(float* acc, uint4 u, float w) {
    float2 f;
    f = __half22float2(*(__half2*)&u.x); acc[0] += w * f.x; acc[1] += w * f.y;
    f = __half22float2(*(__half2*)&u.y); acc[2] += w * f.x; acc[3] += w * f.y;
    f = __half22float2(*(__half2*)&u.z); acc[4] += w * f.x; acc[5] += w * f.y;
    f = __half22float2(*(__half2*)&u.w); acc[6] += w * f.x; acc[7] += w * f.y;
}

// ---------------- fused CSR aggregation: conv1 (warp/node, LDG.128 gathers) --
__global__ void k_agg1(const float* __restrict__ b1) {
    int node = blockIdx.x * 8 + (threadIdx.x >> 5);
    if (node >= NN) return;
    int lane = threadIdx.x & 31;
    int h = lane & 3;
    int headA = lane >> 4;       // 0 or 1
    int headB = 2 + headA;       // 2 or 3
    int beg = g_rowptr[node], end = g_rowptr[node + 1];
    float adst = g_adst1[node * 4 + h];
    float den = 0.f;
    float accA[8], accB[8];
#pragma unroll
    for (int k = 0; k < 8; k++) { accA[k] = 0.f; accB[k] = 0.f; }
    int i = beg;
    for (; i + 2 <= end; i += 2) {
        int s0 = g_csrc[i], s1 = g_csrc[i + 1];
        float x0 = g_asrc1[s0 * 4 + h] + adst; x0 = x0 > 0.f ? x0 : 0.2f * x0;
        float x1 = g_asrc1[s1 * 4 + h] + adst; x1 = x1 > 0.f ? x1 : 0.2f * x1;
        float w0 = __expf(x0), w1 = __expf(x1);
        den += w0 + w1;
        float wA0 = __shfl_sync(0xffffffffu, w0, headA);
        float wB0 = __shfl_sync(0xffffffffu, w0, headB);
        float wA1 = __shfl_sync(0xffffffffu, w1, headA);
        float wB1 = __shfl_sync(0xffffffffu, w1, headB);
        const uint4* p0 = (const uint4*)(g_h1h + (size_t)s0 * 512);
        const uint4* p1 = (const uint4*)(g_h1h + (size_t)s1 * 512);
        uint4 A0 = p0[lane], B0 = p0[32 + lane];
        uint4 A1 = p1[lane], B1 = p1[32 + lane];
        acc8(accA, A0, wA0); acc8(accB, B0, wB0);
        acc8(accA, A1, wA1); acc8(accB, B1, wB1);
    }
    if (i < end) {
        int s0 = g_csrc[i];
        float x0 = g_asrc1[s0 * 4 + h] + adst; x0 = x0 > 0.f ? x0 : 0.2f * x0;
        float w0 = __expf(x0);
        den += w0;
        float wA0 = __shfl_sync(0xffffffffu, w0, headA);
        float wB0 = __shfl_sync(0xffffffffu, w0, headB);
        const uint4* p0 = (const uint4*)(g_h1h + (size_t)s0 * 512);
        uint4 A0 = p0[lane], B0 = p0[32 + lane];
        acc8(accA, A0, wA0); acc8(accB, B0, wB0);
    }
    float dhA = __shfl_sync(0xffffffffu, den, headA);
    float dhB = __shfl_sync(0xffffffffu, den, headB);
    float invA = 1.f / (dhA + 1e-16f);
    float invB = 1.f / (dhB + 1e-16f);
    const float4* bp = (const float4*)b1;
    float4 bA0 = bp[2 * lane], bA1 = bp[2 * lane + 1];
    float4 bB0 = bp[64 + 2 * lane], bB1 = bp[64 + 2 * lane + 1];
    float vA[8], vB[8];
    vA[0] = accA[0] * invA + bA0.x; vA[1] = accA[1] * invA + bA0.y;
    vA[2] = accA[2] * invA + bA0.z; vA[3] = accA[3] * invA + bA0.w;
    vA[4] = accA[4] * invA + bA1.x; vA[5] = accA[5] * invA + bA1.y;
    vA[6] = accA[6] * invA + bA1.z; vA[7] = accA[7] * invA + bA1.w;
    vB[0] = accB[0] * invB + bB0.x; vB[1] = accB[1] * invB + bB0.y;
    vB[2] = accB[2] * invB + bB0.z; vB[3] = accB[3] * invB + bB0.w;
    vB[4] = accB[4] * invB + bB1.x; vB[5] = accB[5] * invB + bB1.y;
    vB[6] = accB[6] * invB + bB1.z; vB[7] = accB[7] * invB + bB1.w;
#pragma unroll
    for (int k = 0; k < 8; k++) {
        vA[k] = vA[k] > 0.f ? vA[k] : expm1f(vA[k]);
        vB[k] = vB[k] > 0.f ? vB[k] : expm1f(vB[k]);
    }
    uint4 oA, oB;
    oA.x = pack_h2(vA[0], vA[1]); oA.y = pack_h2(vA[2], vA[3]);
    oA.z = pack_h2(vA[4], vA[5]); oA.w = pack_h2(vA[6], vA[7]);
    oB.x = pack_h2(vB[0], vB[1]); oB.y = pack_h2(vB[2], vB[3]);
    oB.z = pack_h2(vB[4], vB[5]); oB.w = pack_h2(vB[6], vB[7]);
    uint4* od = (uint4*)(g_out1h + (size_t)node * 512);
    od[lane] = oA;
    od[32 + lane] = oB;
}

// ---------------- fused CSR aggregation: conv2 (warp/node, LDG.64 gathers) ---
__global__ void k_agg2(const float* __restrict__ b2) {
    int node = blockIdx.x * 8 + (threadIdx.x >> 5);
    if (node >= NN) return;
    int lane = threadIdx.x & 31;
    int beg = g_rowptr[node], end = g_rowptr[node + 1];
    float adst = g_adst2[node];
    float den = 0.f;
    float acc[4] = {0.f, 0.f, 0.f, 0.f};
    int i = beg;
    for (; i + 2 <= end; i += 2) {
        int s0 = g_csrc[i], s1 = g_csrc[i + 1];
        float x0 = g_asrc2[s0] + adst; x0 = x0 > 0.f ? x0 : 0.2f * x0;
        float x1 = g_asrc2[s1] + adst; x1 = x1 > 0.f ? x1 : 0.2f * x1;
        float w0 = __expf(x0), w1 = __expf(x1);
        den += w0 + w1;
        uint2 U0 = ((const uint2*)(g_h2h + (size_t)s0 * 128))[lane];
        uint2 U1 = ((const uint2*)(g_h2h + (size_t)s1 * 128))[lane];
        float2 f;
        f = __half22float2(*(__half2*)&U0.x); acc[0] += w0 * f.x; acc[1] += w0 * f.y;
        f = __half22float2(*(__half2*)&U0.y); acc[2] += w0 * f.x; acc[3] += w0 * f.y;
        f = __half22float2(*(__half2*)&U1.x); acc[0] += w1 * f.x; acc[1] += w1 * f.y;
        f = __half22float2(*(__half2*)&U1.y); acc[2] += w1 * f.x; acc[3] += w1 * f.y;
    }
    if (i < end) {
        int s0 = g_csrc[i];
        float x0 = g_asrc2[s0] + adst; x0 = x0 > 0.f ? x0 : 0.2f * x0;
        float w0 = __expf(x0);
        den += w0;
        uint2 U0 = ((const uint2*)(g_h2h + (size_t)s0 * 128))[lane];
        float2 f;
        f = __half22float2(*(__half2*)&U0.x); acc[0] += w0 * f.x; acc[1] += w0 * f.y;
        f = __half22float2(*(__half2*)&U0.y); acc[2] += w0 * f.x; acc[3] += w0 * f.y;
    }
    float inv = 1.f / (den + 1e-16f);
    float4 bb = ((const float4*)b2)[lane];
    float v0 = acc[0] * inv + bb.x;
    float v1 = acc[1] * inv + bb.y;
    float v2 = acc[2] * inv + bb.z;
    float v3 = acc[3] * inv + bb.w;
    v0 = v0 > 0.f ? v0 : expm1f(v0);
    v1 = v1 > 0.f ? v1 : expm1f(v1);
    v2 = v2 > 0.f ? v2 : expm1f(v2);
    v3 = v3 > 0.f ? v3 : expm1f(v3);
    ((float4*)(g_out2 + (size_t)node * 128))[lane] = make_float4(v0, v1, v2, v3);
}

// ---------------- global max pool (parallel, segment flush) ------------------
__global__ void k_pool(const int* __restrict__ batch) {
    int base = blockIdx.x * 128;
    int c = threadIdx.x;  // 128
    int lim = base + 128; if (lim > NN) lim = NN;
    int curg = batch[base];
    float mx = -3.4e38f;
    for (int n = base; n < lim; n++) {
        int g = batch[n];
        if (g != curg) {
            atomicMaxF(&g_pooled[curg * 128 + c], mx);
            curg = g;
            mx = -3.4e38f;
        }
        mx = fmaxf(mx, g_out2[(size_t)n * 128 + c]);
    }
    atomicMaxF(&g_pooled[curg * 128 + c], mx);
}

// ---------------- classifier --------------------------------------------------
__global__ void k_cls(const float* __restrict__ Wc1, const float* __restrict__ bc1,
                      const float* __restrict__ Wc2, const float* __restrict__ bc2,
                      float* __restrict__ out) {
    int g = blockIdx.x;
    int t = threadIdx.x;  // 64
    __shared__ float sp[128];
    __shared__ float sh[64];
    sp[t] = g_pooled[g * 128 + t];
    sp[t + 64] = g_pooled[g * 128 + 64 + t];
    __syncthreads();
    float s = bc1[t];
    for (int k = 0; k < 128; k++) s += sp[k] * Wc1[k * 64 + t];
    sh[t] = fmaxf(s, 0.f);
    __syncthreads();
    if (t < NCLS) {
        float o = bc2[t];
        for (int k = 0; k < 64; k++) o += sh[k] * Wc2[k * NCLS + t];
        out[g * NCLS + t] = o;
    }
}

// ---------------- launch ------------------------------------------------------
extern "C" void kernel_launch(void* const* d_in, const int* in_sizes, int n_in,
                              void* d_out, int out_size) {
    const float* xs    = (const float*)d_in[0];
    const int*   xop   = (const int*)d_in[1];
    const int*   xsrc  = (const int*)d_in[2];
    const int*   xsink = (const int*)d_in[3];
    const int*   xstr  = (const int*)d_in[4];
    const int*   xpay  = (const int*)d_in[5];
    const int*   ei    = (const int*)d_in[6];
    const int*   batch = (const int*)d_in[7];
    const float* eop   = (const float*)d_in[8];
    const float* esrc  = (const float*)d_in[9];
    const float* esink = (const float*)d_in[10];
    const float* estr  = (const float*)d_in[11];
    const float* epay  = (const float*)d_in[12];
    const float* ln_g  = (const float*)d_in[13];
    const float* ln_b  = (const float*)d_in[14];
    const float* W1    = (const float*)d_in[15];
    const float* as1   = (const float*)d_in[16];
    const float* ad1   = (const float*)d_in[17];
    const float* b1    = (const float*)d_in[18];
    const float* W2    = (const float*)d_in[19];
    const float* as2   = (const float*)d_in[20];
    const float* ad2   = (const float*)d_in[21];
    const float* b2    = (const float*)d_in[22];
    const float* Wc1   = (const float*)d_in[23];
    const float* bc1   = (const float*)d_in[24];
    const float* Wc2   = (const float*)d_in[25];
    const float* bc2   = (const float*)d_in[26];
    float* out = (float*)d_out;

    __half *p_featsh, *p_h1h, *p_out1h, *p_h2h;
    cudaGetSymbolAddress((void**)&p_featsh, g_featsh);
    cudaGetSymbolAddress((void**)&p_h1h, g_h1h);
    cudaGetSymbolAddress((void**)&p_out1h, g_out1h);
    cudaGetSymbolAddress((void**)&p_h2h, g_h2h);

    // one-time resource init (no device memory involved)
    static cudaStream_t s_csr = nullptr;
    static cudaEvent_t ev_fork = nullptr, ev_join = nullptr;
    if (s_csr == nullptr) {
        cudaStreamCreateWithFlags(&s_csr, cudaStreamNonBlocking);
        cudaEventCreateWithFlags(&ev_fork, cudaEventDisableTiming);
        cudaEventCreateWithFlags(&ev_join, cudaEventDisableTiming);
    }

    int eb = (ET + 255) / 256;
    int nwb = (NN + 7) / 8;  // warp-per-node blocks (256 thr)

    // ---- fork: CSR build on side stream (only k_agg1 depends on it) ----
    cudaEventRecord(ev_fork, 0);
    cudaStreamWaitEvent(s_csr, ev_fork, 0);
    k_zerodeg<<<(NN + 255) / 256, 256, 0, s_csr>>>();
    k_deg<<<eb, 256, 0, s_csr>>>(ei);
    k_scan<<<1, 1024, 0, s_csr>>>();
    k_fill<<<eb, 256, 0, s_csr>>>(ei);
    cudaEventRecord(ev_join, s_csr);

    // ---- main path: P1T/pooled init, features, conv1 GEMM ----
    k_init<<<32, 256>>>(W1, as1, ad1);
    k_feats<<<NN, 256>>>(xs, xop, xsrc, xsink, xstr, xpay,
                         eop, esrc, esink, estr, epay, ln_g, ln_b);
    {
        dim3 grid(512 / 128, (NN + 127) / 128);
        k_hgemm<<<grid, 256>>>(p_featsh, W1, p_h1h, NN, 512, 256);
    }

    // ---- join CSR before aggregation ----
    cudaStreamWaitEvent(0, ev_join, 0);
    k_agg1<<<nwb, 256>>>(b1);

    // conv2
    {
        dim3 grid(1, (NN + 127) / 128);
        k_hgemm<<<grid, 256>>>(p_out1h, W2, p_h2h, NN, 128, 512);
    }
    k_att2<<<nwb, 256>>>(as2, ad2);
    k_agg2<<<nwb, 256>>>(b2);

    // pool + classify
    k_pool<<<(NN + 127) / 128, 128>>>(batch);
    k_cls<<<GG, 64>>>(Wc1, bc1, Wc2, bc2, out);
}